// round 4
// baseline (speedup 1.0000x reference)
#include <cuda_runtime.h>

// Problem constants
#define BB 2
#define NN 512
#define FF 128
#define HH 256          // 2F
#define NEG_SLOPE 0.04f
#define MASK_VAL  (-9e15f)

#define BN (BB*NN)      // 1024 rows total

// Scratch: PB[bn][h] = p + b1 (row-major, h contiguous)
//          QT[h][bn] = q      (transposed: bn contiguous per h)
__device__ float g_PB[BN * HH];
__device__ float g_QT[HH * BN];

// ---------------------------------------------------------------------------
// Kernel 1: fused p/q projection.
//   p[bn,h] = sum_f x[bn,f] * w1[h, f]
//   q[bn,h] = sum_f x[bn,f] * w1[h, 128+f]
// 128 blocks x 256 threads; block handles 8 consecutive bn rows; thread = h.
// ---------------------------------------------------------------------------
__global__ __launch_bounds__(256) void pq_kernel(
    const float* __restrict__ x,
    const float* __restrict__ w1,
    const float* __restrict__ b1)
{
    __shared__ float xs[8 * FF];          // 8 rows x 128, contiguous in memory
    const int tid = threadIdx.x;
    const int bn0 = blockIdx.x * 8;

    // 8*128 = 1024 floats = 256 float4, one per thread (rows are contiguous)
    ((float4*)xs)[tid] = ((const float4*)(x + (size_t)bn0 * FF))[tid];
    __syncthreads();

    const int h = tid;
    const float* __restrict__ wrow = w1 + (size_t)h * (2 * FF);

    float accP[8], accQ[8];
#pragma unroll
    for (int r = 0; r < 8; ++r) { accP[r] = 0.f; accQ[r] = 0.f; }

#pragma unroll 2
    for (int f = 0; f < FF; f += 4) {
        const float4 wp = *(const float4*)(wrow + f);
        const float4 wq = *(const float4*)(wrow + FF + f);
#pragma unroll
        for (int r = 0; r < 8; ++r) {
            const float x0 = xs[r * FF + f + 0];
            const float x1 = xs[r * FF + f + 1];
            const float x2 = xs[r * FF + f + 2];
            const float x3 = xs[r * FF + f + 3];
            accP[r] = fmaf(x0, wp.x, accP[r]);
            accP[r] = fmaf(x1, wp.y, accP[r]);
            accP[r] = fmaf(x2, wp.z, accP[r]);
            accP[r] = fmaf(x3, wp.w, accP[r]);
            accQ[r] = fmaf(x0, wq.x, accQ[r]);
            accQ[r] = fmaf(x1, wq.y, accQ[r]);
            accQ[r] = fmaf(x2, wq.z, accQ[r]);
            accQ[r] = fmaf(x3, wq.w, accQ[r]);
        }
    }

    const float b1h = b1[h];
#pragma unroll
    for (int r = 0; r < 8; ++r)
        g_PB[(size_t)(bn0 + r) * HH + h] = accP[r] + b1h;

    // Transposed q store: 8 consecutive bn per thread -> two float4 stores
    float4 qa = make_float4(accQ[0], accQ[1], accQ[2], accQ[3]);
    float4 qb = make_float4(accQ[4], accQ[5], accQ[6], accQ[7]);
    *(float4*)(g_QT + (size_t)h * BN + bn0 + 0) = qa;
    *(float4*)(g_QT + (size_t)h * BN + bn0 + 4) = qb;
}

// ---------------------------------------------------------------------------
// Kernel 2: e-scores + leaky + mask + softmax + att@x, fused.
// 128 blocks (b in {0,1} x 64 i-tiles of 8 rows), 256 threads.
// Thread owns j0 = tid, j1 = tid+256; accumulates e over h in smem chunks.
// ---------------------------------------------------------------------------
__global__ __launch_bounds__(256) void attn_kernel(
    const float* __restrict__ x,
    const float* __restrict__ w2,
    const float* __restrict__ b2,
    const int*   __restrict__ adj,
    float* __restrict__ out,
    int write_att)
{
    __shared__ float a_sm[8 * HH];     // 8 KB : PB rows of this i-tile (later: reduction scratch)
    __shared__ float q_sm[8 * NN];     // 16 KB: 8 h-rows x 512 j     (later: attention tile)
    __shared__ float w2_sm[HH];        // 1 KB

    const int tid = threadIdx.x;
    const int b   = blockIdx.x >> 6;
    const int it0 = (blockIdx.x & 63) << 3;

#pragma unroll
    for (int ti = 0; ti < 8; ++ti)
        a_sm[ti * HH + tid] = g_PB[(size_t)(b * NN + it0 + ti) * HH + tid];
    w2_sm[tid] = w2[tid];

    float e0[8], e1[8];
#pragma unroll
    for (int ti = 0; ti < 8; ++ti) { e0[ti] = 0.f; e1[ti] = 0.f; }

    const float* __restrict__ qtb = g_QT + (size_t)b * NN;   // + h*BN + j

    for (int h0 = 0; h0 < HH; h0 += 8) {
        __syncthreads();   // previous chunk fully consumed
        // load q_sm[8][512]: 4096 floats = 1024 float4, 4 per thread, coalesced
#pragma unroll
        for (int l = 0; l < 4; ++l) {
            const int fi = tid + 256 * l;       // float4 index in tile
            const int hc = fi >> 7;             // 128 float4 per 512-float row
            const int jf = fi & 127;
            ((float4*)q_sm)[fi] =
                ((const float4*)(qtb + (size_t)(h0 + hc) * BN))[jf];
        }
        __syncthreads();

#pragma unroll
        for (int hc = 0; hc < 8; ++hc) {
            const float q0 = q_sm[hc * NN + tid];          // conflict-free
            const float q1 = q_sm[hc * NN + 256 + tid];    // conflict-free
            const float w  = w2_sm[h0 + hc];               // broadcast
#pragma unroll
            for (int ti = 0; ti < 8; ++ti) {
                const float av = a_sm[ti * HH + h0 + hc];  // broadcast
                const float t0 = fmaxf(av + q0, 0.f);
                const float t1 = fmaxf(av + q1, 0.f);
                e0[ti] = fmaf(t0, w, e0[ti]);
                e1[ti] = fmaf(t1, w, e1[ti]);
            }
        }
    }

    // leaky relu + adjacency mask
    const float b2v = b2[0];
    const int* __restrict__ adjb = adj + ((size_t)b * NN + it0) * NN;
#pragma unroll
    for (int ti = 0; ti < 8; ++ti) {
        const int m0 = adjb[(size_t)ti * NN + tid];
        const int m1 = adjb[(size_t)ti * NN + 256 + tid];
        float v0 = e0[ti] + b2v;
        float v1 = e1[ti] + b2v;
        v0 = (v0 > 0.f) ? v0 : NEG_SLOPE * v0;
        v1 = (v1 > 0.f) ? v1 : NEG_SLOPE * v1;
        e0[ti] = (m0 > 0) ? v0 : MASK_VAL;
        e1[ti] = (m1 > 0) ? v1 : MASK_VAL;
    }

    // ---- softmax over j (512 values spread: 2 per thread), per ti row ----
    float* red = a_sm;                 // reuse (a_sm no longer needed)
    __syncthreads();
#pragma unroll
    for (int ti = 0; ti < 8; ++ti)
        red[ti * HH + tid] = fmaxf(e0[ti], e1[ti]);
    __syncthreads();
    for (int s = 128; s > 0; s >>= 1) {
        if (tid < s) {
#pragma unroll
            for (int ti = 0; ti < 8; ++ti)
                red[ti * HH + tid] = fmaxf(red[ti * HH + tid], red[ti * HH + tid + s]);
        }
        __syncthreads();
    }
    float mx[8];
#pragma unroll
    for (int ti = 0; ti < 8; ++ti) mx[ti] = red[ti * HH];
    __syncthreads();

#pragma unroll
    for (int ti = 0; ti < 8; ++ti) {
        e0[ti] = __expf(e0[ti] - mx[ti]);
        e1[ti] = __expf(e1[ti] - mx[ti]);
        red[ti * HH + tid] = e0[ti] + e1[ti];
    }
    __syncthreads();
    for (int s = 128; s > 0; s >>= 1) {
        if (tid < s) {
#pragma unroll
            for (int ti = 0; ti < 8; ++ti)
                red[ti * HH + tid] += red[ti * HH + tid + s];
        }
        __syncthreads();
    }
    float inv[8];
#pragma unroll
    for (int ti = 0; ti < 8; ++ti) inv[ti] = 1.0f / red[ti * HH];
    __syncthreads();

    // attention values -> smem (reuse q_sm as att[8][512])
    float* att = q_sm;
#pragma unroll
    for (int ti = 0; ti < 8; ++ti) {
        att[ti * NN + tid]       = e0[ti] * inv[ti];
        att[ti * NN + 256 + tid] = e1[ti] * inv[ti];
    }
    __syncthreads();

    // attention[0,0,:] output (block 0 holds b=0, i=0 at ti=0)
    if (write_att && blockIdx.x == 0) {
        out[BB * NN * FF + tid]       = att[tid];
        out[BB * NN * FF + 256 + tid] = att[256 + tid];
    }

    // ---- next_h[b, it0+ti, f] = sum_j att[ti][j] * x[b, j, f] ----
    const int g = tid >> 7;            // 0: ti 0..3, 1: ti 4..7
    const int f = tid & 127;
    const float* __restrict__ xb = x + (size_t)b * NN * FF;
    const float* __restrict__ arow = att + (size_t)(g * 4) * NN;

    float a0 = 0.f, a1 = 0.f, a2 = 0.f, a3 = 0.f;
#pragma unroll 4
    for (int j = 0; j < NN; ++j) {
        const float xv = xb[(size_t)j * FF + f];           // coalesced
        a0 = fmaf(arow[j],            xv, a0);             // broadcast LDS
        a1 = fmaf(arow[NN + j],       xv, a1);
        a2 = fmaf(arow[2 * NN + j],   xv, a2);
        a3 = fmaf(arow[3 * NN + j],   xv, a3);
    }
    float* __restrict__ orow = out + (size_t)(b * NN + it0 + g * 4) * FF + f;
    orow[0 * FF] = a0;
    orow[1 * FF] = a1;
    orow[2 * FF] = a2;
    orow[3 * FF] = a3;
}

// ---------------------------------------------------------------------------
// Launch. Input order per setup_inputs: x, w1, b1, w2, b2, adj
// Output: next_h (2*512*128 floats) then attention[0,0,:] (512 floats)
// ---------------------------------------------------------------------------
extern "C" void kernel_launch(void* const* d_in, const int* in_sizes, int n_in,
                              void* d_out, int out_size)
{
    const float* x   = (const float*)d_in[0];
    const float* w1  = (const float*)d_in[1];
    const float* b1  = (const float*)d_in[2];
    const float* w2  = (const float*)d_in[3];
    const float* b2  = (const float*)d_in[4];
    const int*   adj = (const int*)  d_in[5];
    float* out = (float*)d_out;

    const int write_att = (out_size >= BB * NN * FF + NN) ? 1 : 0;

    pq_kernel<<<BN / 8, 256>>>(x, w1, b1);
    attn_kernel<<<BB * (NN / 8), 256>>>(x, w2, b2, adj, out, write_att);
}